// round 12
// baseline (speedup 1.0000x reference)
#include <cuda_runtime.h>
#include <math.h>

#define BB   128
#define GG   37
#define NP   (GG*GG)          // 1369 patches
#define DD   768
#define CC   5                // cues: cls + 4 regs
#define SS   (1 + 4 + NP)     // 1374 tokens per batch
#define CH   9                // chunks per batch: 128*9 = 1152 blocks = 592+560 (balanced waves)
#define CPB  ((NP + CH - 1) / CH)   // 153 patches per chunk
#define NW   8                // warps per block
#define PP   4                // patches per warp per inner iteration
#define FLT_BIG 3.402823466e38f

// Cross-block scratch: per (batch, cue, chunk) partial argmax + done counters.
__device__ float g_pval[BB * CC * CH];
__device__ int   g_pidx[BB * CC * CH];
__device__ int   g_done[BB];          // zero-init; each launch leaves it zeroed

// ---------------------------------------------------------------------------
// Fused kernel: streaming cue.patch argmax per chunk; the LAST finishing block
// of each batch (threadFenceReduction pattern) pools + normalizes that batch.
// Grid: (BB, CH). Block: 256 threads (8 warps), 4 CTAs/SM pinned.
// ---------------------------------------------------------------------------
__global__ __launch_bounds__(256, 4)
void fused_kernel(const float* __restrict__ tokens, float* __restrict__ out)
{
    __shared__ float cue_s[CC * DD];     // 15360 B — cues stay resident for pooling
    __shared__ float s_bval[NW * CC];
    __shared__ int   s_bidx[NW * CC];
    __shared__ int   s_win[4];
    __shared__ float s_red[18];
    __shared__ int   s_last;

    const int b     = blockIdx.x;
    const int chunk = blockIdx.y;
    const int tid   = threadIdx.x;
    const int w     = tid >> 5;
    const int lane  = tid & 31;

    const float* tb = tokens + (size_t)b * SS * DD;

    // stage the 5 cue rows (tokens s = 0..4) into shared memory
    for (int i = tid; i < CC * DD; i += 256) cue_s[i] = tb[i];
    __syncthreads();

    const int start = chunk * CPB;
    const int end   = min(start + CPB, NP);

    float bval[CC];
    int   bidx[CC];
#pragma unroll
    for (int c = 0; c < CC; c++) { bval[c] = -FLT_BIG; bidx[c] = 0x7fffffff; }

    const float4* cue4 = reinterpret_cast<const float4*>(cue_s);
    const float4* pb4  = reinterpret_cast<const float4*>(tb + 5 * DD);

    for (int base = start + w * PP; base < end; base += NW * PP) {

        float acc[CC][PP];
#pragma unroll
        for (int c = 0; c < CC; c++)
#pragma unroll
            for (int i = 0; i < PP; i++) acc[c][i] = 0.0f;

        // limited unroll keeps only one j-step of patch data (16 regs) live
#pragma unroll 2
        for (int j = 0; j < 6; j++) {              // 6 * 32 float4 = 768 floats
            const int off = j * 32 + lane;
            float4 v[PP];
#pragma unroll
            for (int i = 0; i < PP; i++) {
                if (base + i < end) {
                    v[i] = __ldcs(&pb4[(size_t)(base + i) * 192 + off]);
                } else {
                    v[i] = make_float4(0.f, 0.f, 0.f, 0.f);
                }
            }
#pragma unroll
            for (int c = 0; c < CC; c++) {
                const float4 q = cue4[c * 192 + off];
#pragma unroll
                for (int i = 0; i < PP; i++) {
                    acc[c][i] += v[i].x * q.x + v[i].y * q.y
                               + v[i].z * q.z + v[i].w * q.w;
                }
            }
        }

        // warp-butterfly reduce the 20 partial dots; argmax with first-index ties
#pragma unroll
        for (int c = 0; c < CC; c++) {
#pragma unroll
            for (int i = 0; i < PP; i++) {
                float v = acc[c][i];
                v += __shfl_xor_sync(0xffffffffu, v, 16);
                v += __shfl_xor_sync(0xffffffffu, v, 8);
                v += __shfl_xor_sync(0xffffffffu, v, 4);
                v += __shfl_xor_sync(0xffffffffu, v, 2);
                v += __shfl_xor_sync(0xffffffffu, v, 1);
                const int p = base + i;
                if (p < end) {
                    if (v > bval[c] || (v == bval[c] && p < bidx[c])) {
                        bval[c] = v;
                        bidx[c] = p;
                    }
                }
            }
        }
    }

    if (lane == 0) {
#pragma unroll
        for (int c = 0; c < CC; c++) {
            s_bval[w * CC + c] = bval[c];
            s_bidx[w * CC + c] = bidx[c];
        }
    }
    __syncthreads();

    if (tid < CC) {
        const int c = tid;
        float bv = -FLT_BIG;
        int   bi = 0x7fffffff;
        for (int ww = 0; ww < NW; ww++) {
            float v  = s_bval[ww * CC + c];
            int   ix = s_bidx[ww * CC + c];
            if (v > bv || (v == bv && ix < bi)) { bv = v; bi = ix; }
        }
        g_pval[(b * CC + c) * CH + chunk] = bv;
        g_pidx[(b * CC + c) * CH + chunk] = bi;
        __threadfence();                 // make partials device-visible
    }
    __syncthreads();

    if (tid == 0) {
        const int old = atomicAdd(&g_done[b], 1);
        s_last = (old == CH - 1);
    }
    __syncthreads();
    if (!s_last) return;

    // ------------------- last block for batch b: pool + normalize -------------------
    __threadfence();                     // order partial reads after counter observation

    for (int c = 0; c < CC; c++) {
        // warp 0: parallel merge of the CH chunk partials
        if (tid < 32) {
            float bv = -FLT_BIG;
            int   bi = 0x7fffffff;
            if (tid < CH) {
                bv = g_pval[(b * CC + c) * CH + tid];
                bi = g_pidx[(b * CC + c) * CH + tid];
            }
#pragma unroll
            for (int o = 16; o; o >>= 1) {
                float ov = __shfl_xor_sync(0xffffffffu, bv, o);
                int   oi = __shfl_xor_sync(0xffffffffu, bi, o);
                if (ov > bv || (ov == bv && oi < bi)) { bv = ov; bi = oi; }
            }
            if (tid == 0) {
                const int h = bi / GG;
                const int ww = bi % GG;
                s_win[0] = max(h - 1, 0);
                s_win[1] = min(h + 1, GG - 1);
                s_win[2] = max(ww - 1, 0);
                s_win[3] = min(ww + 1, GG - 1);
            }
        }
        __syncthreads();

        const int h0 = s_win[0], h1 = s_win[1], w0 = s_win[2], w1 = s_win[3];
        const float inv_count = 1.0f / (float)((h1 - h0 + 1) * (w1 - w0 + 1));

        // each thread handles dims d = tid, tid+256, tid+512 (sequential k keeps regs low)
        float roi_k[3];
        float sr = 0.0f, sq = 0.0f;
#pragma unroll 1
        for (int k = 0; k < 3; k++) {
            const int d = tid + 256 * k;
            float s = 0.0f;
#pragma unroll
            for (int hh = 0; hh < 3; hh++) {
#pragma unroll
                for (int ww2 = 0; ww2 < 3; ww2++) {
                    const int h = h0 + hh;
                    const int ww = w0 + ww2;
                    float val = 0.0f;
                    if (h <= h1 && ww <= w1)
                        val = tb[(size_t)(5 + h * GG + ww) * DD + d];
                    s += val;
                }
            }
            roi_k[k] = s * inv_count;
            const float q = cue_s[c * DD + d];
            sr += roi_k[k] * roi_k[k];
            sq += q * q;
        }

        // block-reduce the two squared norms
#pragma unroll
        for (int o = 16; o; o >>= 1) {
            sr += __shfl_xor_sync(0xffffffffu, sr, o);
            sq += __shfl_xor_sync(0xffffffffu, sq, o);
        }
        if (lane == 0) { s_red[w] = sr; s_red[8 + w] = sq; }
        __syncthreads();
        if (tid == 0) {
            float a = 0.0f, bs = 0.0f;
            for (int i = 0; i < NW; i++) { a += s_red[i]; bs += s_red[8 + i]; }
            s_red[16] = a;
            s_red[17] = bs;
        }
        __syncthreads();

        const float rinv = 1.0f / fmaxf(sqrtf(s_red[16]), 1e-12f);
        const float qinv = 1.0f / fmaxf(sqrtf(s_red[17]), 1e-12f);

        float* ob = out + (size_t)b * 10 * DD;
#pragma unroll 1
        for (int k = 0; k < 3; k++) {
            const int d = tid + 256 * k;
            ob[(size_t)c * DD + d]       = cue_s[c * DD + d] * qinv;  // normalized cue
            ob[(size_t)(5 + c) * DD + d] = roi_k[k] * rinv;           // normalized roi
        }
        __syncthreads();    // protect s_win / s_red before next cue iteration
    }

    if (tid == 0) g_done[b] = 0;    // reset for next launch (deterministic replays)
}

extern "C" void kernel_launch(void* const* d_in, const int* in_sizes, int n_in,
                              void* d_out, int out_size)
{
    const float* tokens = (const float*)d_in[0];
    float* out = (float*)d_out;

    dim3 g1(BB, CH);     // 128 x 9 = 1152 blocks
    fused_kernel<<<g1, 256>>>(tokens, out);
}

// round 14
// speedup vs baseline: 1.3707x; 1.3707x over previous
#include <cuda_runtime.h>
#include <math.h>

#define BB   128
#define GG   37
#define NP   (GG*GG)          // 1369 patches
#define DD   768
#define CC   5                // cues: cls + 4 regs
#define SS   (1 + 4 + NP)     // 1374 tokens per batch
#define CH   9                // chunks per batch: 128*9 = 1152 blocks = 592+560 (balanced waves)
#define CPB  ((NP + CH - 1) / CH)   // 153 patches per chunk
#define NW   8                // warps per block
#define PP   4                // patches per warp per inner iteration
#define FLT_BIG 3.402823466e38f

// Cross-kernel scratch: per (batch, cue, chunk) partial argmax.
__device__ float g_pval[BB * CC * CH];
__device__ int   g_pidx[BB * CC * CH];

// ---------------------------------------------------------------------------
// Kernel 1: streaming dot-products cue[c] . patch[p], per-chunk argmax.
// Grid: (BB, CH). Block: 256 threads (8 warps), 4 CTAs/SM pinned (regs<=64).
// Byte-identical to the validated R11 kernel — near its streaming roofline.
// ---------------------------------------------------------------------------
__global__ __launch_bounds__(256, 4)
void sim_argmax_kernel(const float* __restrict__ tokens)
{
    __shared__ float cue_s[CC * DD];     // 15360 B
    __shared__ float s_bval[NW * CC];
    __shared__ int   s_bidx[NW * CC];

    const int b     = blockIdx.x;
    const int chunk = blockIdx.y;
    const int tid   = threadIdx.x;
    const int w     = tid >> 5;
    const int lane  = tid & 31;

    const float* tb = tokens + (size_t)b * SS * DD;

    // stage the 5 cue rows (tokens s = 0..4) into shared memory
    for (int i = tid; i < CC * DD; i += 256) cue_s[i] = tb[i];
    __syncthreads();

    const int start = chunk * CPB;
    const int end   = min(start + CPB, NP);

    float bval[CC];
    int   bidx[CC];
#pragma unroll
    for (int c = 0; c < CC; c++) { bval[c] = -FLT_BIG; bidx[c] = 0x7fffffff; }

    const float4* cue4 = reinterpret_cast<const float4*>(cue_s);
    const float4* pb4  = reinterpret_cast<const float4*>(tb + 5 * DD);

    for (int base = start + w * PP; base < end; base += NW * PP) {

        float acc[CC][PP];
#pragma unroll
        for (int c = 0; c < CC; c++)
#pragma unroll
            for (int i = 0; i < PP; i++) acc[c][i] = 0.0f;

        // limited unroll keeps only one j-step of patch data (16 regs) live
#pragma unroll 2
        for (int j = 0; j < 6; j++) {              // 6 * 32 float4 = 768 floats
            const int off = j * 32 + lane;
            float4 v[PP];
#pragma unroll
            for (int i = 0; i < PP; i++) {
                // predicated streaming load: tail lanes contribute 0, no traffic
                if (base + i < end) {
                    v[i] = __ldcs(&pb4[(size_t)(base + i) * 192 + off]);
                } else {
                    v[i] = make_float4(0.f, 0.f, 0.f, 0.f);
                }
            }
#pragma unroll
            for (int c = 0; c < CC; c++) {
                const float4 q = cue4[c * 192 + off];
#pragma unroll
                for (int i = 0; i < PP; i++) {
                    acc[c][i] += v[i].x * q.x + v[i].y * q.y
                               + v[i].z * q.z + v[i].w * q.w;
                }
            }
        }

        // warp-butterfly reduce the 20 partial dots; argmax with first-index ties
#pragma unroll
        for (int c = 0; c < CC; c++) {
#pragma unroll
            for (int i = 0; i < PP; i++) {
                float v = acc[c][i];
                v += __shfl_xor_sync(0xffffffffu, v, 16);
                v += __shfl_xor_sync(0xffffffffu, v, 8);
                v += __shfl_xor_sync(0xffffffffu, v, 4);
                v += __shfl_xor_sync(0xffffffffu, v, 2);
                v += __shfl_xor_sync(0xffffffffu, v, 1);
                const int p = base + i;
                if (p < end) {
                    if (v > bval[c] || (v == bval[c] && p < bidx[c])) {
                        bval[c] = v;
                        bidx[c] = p;
                    }
                }
            }
        }
    }

    if (lane == 0) {
#pragma unroll
        for (int c = 0; c < CC; c++) {
            s_bval[w * CC + c] = bval[c];
            s_bidx[w * CC + c] = bidx[c];
        }
    }
    __syncthreads();

    if (tid < CC) {
        const int c = tid;
        float bv = -FLT_BIG;
        int   bi = 0x7fffffff;
        for (int ww = 0; ww < NW; ww++) {
            float v  = s_bval[ww * CC + c];
            int   ix = s_bidx[ww * CC + c];
            if (v > bv || (v == bv && ix < bi)) { bv = v; bi = ix; }
        }
        g_pval[(b * CC + c) * CH + chunk] = bv;
        g_pidx[(b * CC + c) * CH + chunk] = bi;
    }
}

// ---------------------------------------------------------------------------
// Kernel 2: merge chunk partials (parallel, warp 0) -> argmax (h,w);
// 3x3 clipped window mean; L2-normalize roi and cue; write (B, 10, 768).
// Grid: (CC, BB). Block: 256 threads; thread t owns dims t, t+256, t+512.
// All 27 window loads issued back-to-back (3x per-thread MLP vs R11) and
// 256-thread blocks allow up to 8 CTAs/SM (vs 2 with 768-thread blocks):
// this kernel is latency-bound, so concurrency is the lever.
// ---------------------------------------------------------------------------
__global__ __launch_bounds__(256)
void pool_norm_kernel(const float* __restrict__ tokens, float* __restrict__ out)
{
    const int c   = blockIdx.x;
    const int b   = blockIdx.y;
    const int tid = threadIdx.x;

    __shared__ int   s_win[4];     // h0, h1, w0, w1
    __shared__ float s_red[18];

    const float* tb = tokens + (size_t)b * SS * DD;

    // issue the 3 cue loads before the merge/sync so they overlap the chain
    float q[3];
#pragma unroll
    for (int k = 0; k < 3; k++)
        q[k] = tb[(size_t)c * DD + tid + 256 * k];

    // warp 0: parallel merge of the CH chunk partials (first-index tie rule)
    if (tid < 32) {
        float bv = -FLT_BIG;
        int   bi = 0x7fffffff;
        if (tid < CH) {
            bv = g_pval[(b * CC + c) * CH + tid];
            bi = g_pidx[(b * CC + c) * CH + tid];
        }
#pragma unroll
        for (int o = 16; o; o >>= 1) {
            float ov = __shfl_xor_sync(0xffffffffu, bv, o);
            int   oi = __shfl_xor_sync(0xffffffffu, bi, o);
            if (ov > bv || (ov == bv && oi < bi)) { bv = ov; bi = oi; }
        }
        if (tid == 0) {
            const int h = bi / GG;
            const int w = bi % GG;
            s_win[0] = max(h - 1, 0);
            s_win[1] = min(h + 1, GG - 1);
            s_win[2] = max(w - 1, 0);
            s_win[3] = min(w + 1, GG - 1);
        }
    }
    __syncthreads();

    const int h0 = s_win[0], h1 = s_win[1], w0 = s_win[2], w1 = s_win[3];
    const float inv_count = 1.0f / (float)((h1 - h0 + 1) * (w1 - w0 + 1));

    // issue ALL 27 predicated window loads before any arithmetic -> max MLP
    float v[3][9];
#pragma unroll
    for (int k = 0; k < 3; k++) {
        const int d = tid + 256 * k;
#pragma unroll
        for (int hh = 0; hh < 3; hh++) {
#pragma unroll
            for (int ww = 0; ww < 3; ww++) {
                const int h = h0 + hh;
                const int w = w0 + ww;
                float val = 0.0f;
                if (h <= h1 && w <= w1)
                    val = tb[(size_t)(5 + h * GG + w) * DD + d];
                v[k][hh * 3 + ww] = val;
            }
        }
    }

    float roi[3];
    float sr = 0.0f, sq = 0.0f;
#pragma unroll
    for (int k = 0; k < 3; k++) {
        float s = 0.0f;
#pragma unroll
        for (int i = 0; i < 9; i++) s += v[k][i];
        roi[k] = s * inv_count;
        sr += roi[k] * roi[k];
        sq += q[k] * q[k];
    }

    // block-reduce the two squared norms (8 warps)
#pragma unroll
    for (int o = 16; o; o >>= 1) {
        sr += __shfl_xor_sync(0xffffffffu, sr, o);
        sq += __shfl_xor_sync(0xffffffffu, sq, o);
    }
    const int w = tid >> 5, lane = tid & 31;
    if (lane == 0) { s_red[w] = sr; s_red[8 + w] = sq; }
    __syncthreads();
    if (tid == 0) {
        float a = 0.0f, bs = 0.0f;
        for (int i = 0; i < 8; i++) { a += s_red[i]; bs += s_red[8 + i]; }
        s_red[16] = a;
        s_red[17] = bs;
    }
    __syncthreads();

    const float rinv = 1.0f / fmaxf(sqrtf(s_red[16]), 1e-12f);
    const float qinv = 1.0f / fmaxf(sqrtf(s_red[17]), 1e-12f);

    float* ob = out + (size_t)b * 10 * DD;
#pragma unroll
    for (int k = 0; k < 3; k++) {
        const int d = tid + 256 * k;
        ob[(size_t)c * DD + d]       = q[k] * qinv;      // normalized cue
        ob[(size_t)(5 + c) * DD + d] = roi[k] * rinv;    // normalized roi
    }
}

extern "C" void kernel_launch(void* const* d_in, const int* in_sizes, int n_in,
                              void* d_out, int out_size)
{
    const float* tokens = (const float*)d_in[0];
    float* out = (float*)d_out;

    dim3 g1(BB, CH);     // 128 x 9 = 1152 blocks (2 balanced waves at 4 CTA/SM)
    sim_argmax_kernel<<<g1, 256>>>(tokens);

    dim3 g2(CC, BB);     // 5 x 128 = 640 blocks
    pool_norm_kernel<<<g2, 256>>>(tokens, out);
}

// round 15
// speedup vs baseline: 1.3984x; 1.0202x over previous
#include <cuda_runtime.h>
#include <math.h>

#define BB   128
#define GG   37
#define NP   (GG*GG)          // 1369 patches
#define DD   768
#define CC   5                // cues: cls + 4 regs
#define SS   (1 + 4 + NP)     // 1374 tokens per batch
#define CH   9                // chunks per batch: 128*9 = 1152 blocks = 592+560 (balanced waves)
#define CPB  ((NP + CH - 1) / CH)   // 153 patches per chunk
#define NW   8                // warps per block
#define PP   4                // patches per warp per inner iteration
#define FLT_BIG 3.402823466e38f

// Cross-kernel scratch: per (batch, cue, chunk) partial argmax.
__device__ float g_pval[BB * CC * CH];
__device__ int   g_pidx[BB * CC * CH];

// ---------------------------------------------------------------------------
// Kernel 1: streaming dot-products cue[c] . patch[p], per-chunk argmax.
// Grid: (BB, CH). Block: 256 threads (8 warps), 4 CTAs/SM pinned (regs<=64).
// Streaming loop identical to the validated R11/R14 kernel. Signals PDL
// dependents after its global partials are written.
// ---------------------------------------------------------------------------
__global__ __launch_bounds__(256, 4)
void sim_argmax_kernel(const float* __restrict__ tokens)
{
    __shared__ float cue_s[CC * DD];     // 15360 B
    __shared__ float s_bval[NW * CC];
    __shared__ int   s_bidx[NW * CC];

    const int b     = blockIdx.x;
    const int chunk = blockIdx.y;
    const int tid   = threadIdx.x;
    const int w     = tid >> 5;
    const int lane  = tid & 31;

    const float* tb = tokens + (size_t)b * SS * DD;

    // stage the 5 cue rows (tokens s = 0..4) into shared memory
    for (int i = tid; i < CC * DD; i += 256) cue_s[i] = tb[i];
    __syncthreads();

    const int start = chunk * CPB;
    const int end   = min(start + CPB, NP);

    float bval[CC];
    int   bidx[CC];
#pragma unroll
    for (int c = 0; c < CC; c++) { bval[c] = -FLT_BIG; bidx[c] = 0x7fffffff; }

    const float4* cue4 = reinterpret_cast<const float4*>(cue_s);
    const float4* pb4  = reinterpret_cast<const float4*>(tb + 5 * DD);

    for (int base = start + w * PP; base < end; base += NW * PP) {

        float acc[CC][PP];
#pragma unroll
        for (int c = 0; c < CC; c++)
#pragma unroll
            for (int i = 0; i < PP; i++) acc[c][i] = 0.0f;

        // limited unroll keeps only one j-step of patch data (16 regs) live
#pragma unroll 2
        for (int j = 0; j < 6; j++) {              // 6 * 32 float4 = 768 floats
            const int off = j * 32 + lane;
            float4 v[PP];
#pragma unroll
            for (int i = 0; i < PP; i++) {
                // predicated streaming load: tail lanes contribute 0, no traffic
                if (base + i < end) {
                    v[i] = __ldcs(&pb4[(size_t)(base + i) * 192 + off]);
                } else {
                    v[i] = make_float4(0.f, 0.f, 0.f, 0.f);
                }
            }
#pragma unroll
            for (int c = 0; c < CC; c++) {
                const float4 q = cue4[c * 192 + off];
#pragma unroll
                for (int i = 0; i < PP; i++) {
                    acc[c][i] += v[i].x * q.x + v[i].y * q.y
                               + v[i].z * q.z + v[i].w * q.w;
                }
            }
        }

        // warp-butterfly reduce the 20 partial dots; argmax with first-index ties
#pragma unroll
        for (int c = 0; c < CC; c++) {
#pragma unroll
            for (int i = 0; i < PP; i++) {
                float v = acc[c][i];
                v += __shfl_xor_sync(0xffffffffu, v, 16);
                v += __shfl_xor_sync(0xffffffffu, v, 8);
                v += __shfl_xor_sync(0xffffffffu, v, 4);
                v += __shfl_xor_sync(0xffffffffu, v, 2);
                v += __shfl_xor_sync(0xffffffffu, v, 1);
                const int p = base + i;
                if (p < end) {
                    if (v > bval[c] || (v == bval[c] && p < bidx[c])) {
                        bval[c] = v;
                        bidx[c] = p;
                    }
                }
            }
        }
    }

    if (lane == 0) {
#pragma unroll
        for (int c = 0; c < CC; c++) {
            s_bval[w * CC + c] = bval[c];
            s_bidx[w * CC + c] = bidx[c];
        }
    }
    __syncthreads();

    if (tid < CC) {
        const int c = tid;
        float bv = -FLT_BIG;
        int   bi = 0x7fffffff;
        for (int ww = 0; ww < NW; ww++) {
            float v  = s_bval[ww * CC + c];
            int   ix = s_bidx[ww * CC + c];
            if (v > bv || (v == bv && ix < bi)) { bv = v; bi = ix; }
        }
        g_pval[(b * CC + c) * CH + chunk] = bv;
        g_pidx[(b * CC + c) * CH + chunk] = bi;
    }
    __syncthreads();

    // PDL: allow the dependent pool_norm grid to begin launching. Its reads of
    // g_pval/g_pidx sit behind griddepcontrol.wait (full grid completion), so
    // signaling here only exposes launch/prologue overlap, not our data.
    asm volatile("griddepcontrol.launch_dependents;" ::: "memory");
}

// ---------------------------------------------------------------------------
// Kernel 2: merge chunk partials (parallel, warp 0) -> argmax (h,w);
// 3x3 clipped window mean; L2-normalize roi and cue; write (B, 10, 768).
// Grid: (CC, BB). Block: 256 threads; thread t owns dims t, t+256, t+512.
// PDL secondary: cue loads (independent of kernel 1) are issued BEFORE
// griddepcontrol.wait so they overlap kernel 1's drain.
// ---------------------------------------------------------------------------
__global__ __launch_bounds__(256)
void pool_norm_kernel(const float* __restrict__ tokens, float* __restrict__ out)
{
    const int c   = blockIdx.x;
    const int b   = blockIdx.y;
    const int tid = threadIdx.x;

    __shared__ int   s_win[4];     // h0, h1, w0, w1
    __shared__ float s_red[18];

    const float* tb = tokens + (size_t)b * SS * DD;

    // independent prologue: issue the 3 cue loads before waiting on kernel 1
    float q[3];
#pragma unroll
    for (int k = 0; k < 3; k++)
        q[k] = tb[(size_t)c * DD + tid + 256 * k];

    // wait for kernel 1's grid to fully complete (makes g_pval/g_pidx visible)
    asm volatile("griddepcontrol.wait;" ::: "memory");

    // warp 0: parallel merge of the CH chunk partials (first-index tie rule)
    if (tid < 32) {
        float bv = -FLT_BIG;
        int   bi = 0x7fffffff;
        if (tid < CH) {
            bv = g_pval[(b * CC + c) * CH + tid];
            bi = g_pidx[(b * CC + c) * CH + tid];
        }
#pragma unroll
        for (int o = 16; o; o >>= 1) {
            float ov = __shfl_xor_sync(0xffffffffu, bv, o);
            int   oi = __shfl_xor_sync(0xffffffffu, bi, o);
            if (ov > bv || (ov == bv && oi < bi)) { bv = ov; bi = oi; }
        }
        if (tid == 0) {
            const int h = bi / GG;
            const int w = bi % GG;
            s_win[0] = max(h - 1, 0);
            s_win[1] = min(h + 1, GG - 1);
            s_win[2] = max(w - 1, 0);
            s_win[3] = min(w + 1, GG - 1);
        }
    }
    __syncthreads();

    const int h0 = s_win[0], h1 = s_win[1], w0 = s_win[2], w1 = s_win[3];
    const float inv_count = 1.0f / (float)((h1 - h0 + 1) * (w1 - w0 + 1));

    // issue ALL 27 predicated window loads before any arithmetic -> max MLP
    float v[3][9];
#pragma unroll
    for (int k = 0; k < 3; k++) {
        const int d = tid + 256 * k;
#pragma unroll
        for (int hh = 0; hh < 3; hh++) {
#pragma unroll
            for (int ww = 0; ww < 3; ww++) {
                const int h = h0 + hh;
                const int w = w0 + ww;
                float val = 0.0f;
                if (h <= h1 && w <= w1)
                    val = tb[(size_t)(5 + h * GG + w) * DD + d];
                v[k][hh * 3 + ww] = val;
            }
        }
    }

    float roi[3];
    float sr = 0.0f, sq = 0.0f;
#pragma unroll
    for (int k = 0; k < 3; k++) {
        float s = 0.0f;
#pragma unroll
        for (int i = 0; i < 9; i++) s += v[k][i];
        roi[k] = s * inv_count;
        sr += roi[k] * roi[k];
        sq += q[k] * q[k];
    }

    // block-reduce the two squared norms (8 warps)
#pragma unroll
    for (int o = 16; o; o >>= 1) {
        sr += __shfl_xor_sync(0xffffffffu, sr, o);
        sq += __shfl_xor_sync(0xffffffffu, sq, o);
    }
    const int w = tid >> 5, lane = tid & 31;
    if (lane == 0) { s_red[w] = sr; s_red[8 + w] = sq; }
    __syncthreads();
    if (tid == 0) {
        float a = 0.0f, bs = 0.0f;
        for (int i = 0; i < 8; i++) { a += s_red[i]; bs += s_red[8 + i]; }
        s_red[16] = a;
        s_red[17] = bs;
    }
    __syncthreads();

    const float rinv = 1.0f / fmaxf(sqrtf(s_red[16]), 1e-12f);
    const float qinv = 1.0f / fmaxf(sqrtf(s_red[17]), 1e-12f);

    float* ob = out + (size_t)b * 10 * DD;
#pragma unroll
    for (int k = 0; k < 3; k++) {
        const int d = tid + 256 * k;
        ob[(size_t)c * DD + d]       = q[k] * qinv;      // normalized cue
        ob[(size_t)(5 + c) * DD + d] = roi[k] * rinv;    // normalized roi
    }
}

extern "C" void kernel_launch(void* const* d_in, const int* in_sizes, int n_in,
                              void* d_out, int out_size)
{
    const float* tokens = (const float*)d_in[0];
    float* out = (float*)d_out;

    dim3 g1(BB, CH);     // 128 x 9 = 1152 blocks (2 balanced waves at 4 CTA/SM)
    sim_argmax_kernel<<<g1, 256>>>(tokens);

    // PDL secondary launch: may begin launching once kernel 1's CTAs signal
    // launch_dependents; data reads are gated by griddepcontrol.wait inside.
    cudaLaunchConfig_t cfg = {};
    cfg.gridDim  = dim3(CC, BB);     // 5 x 128 = 640 blocks
    cfg.blockDim = dim3(256);
    cfg.dynamicSmemBytes = 0;
    cfg.stream = 0;
    cudaLaunchAttribute attrs[1];
    attrs[0].id = cudaLaunchAttributeProgrammaticStreamSerialization;
    attrs[0].val.programmaticStreamSerializationAllowed = 1;
    cfg.attrs = attrs;
    cfg.numAttrs = 1;
    cudaLaunchKernelEx(&cfg, pool_norm_kernel, tokens, out);
}